// round 7
// baseline (speedup 1.0000x reference)
#include <cuda_runtime.h>
#include <cuda_fp16.h>
#include <math.h>
#include <stdint.h>

#define BATCH 8
#define NPTS  4096
#define DIM   64
#define TILE  128
#define NT    (NPTS / TILE)            // 32
#define NTRI  (NT * (NT + 1) / 2)      // 528 upper-tri tiles per batch
#define SLOTS 37                       // CTAs per batch
#define GRID  (BATCH * SLOTS)          // 296
#define TPB   256

// smem sub-tile: 128 rows x 72 fp16 (144 B stride) -> conflict-free ldmatrix
#define SROWB   144
#define SUBTILE (128 * SROWB)          // 18432 B
#define BUFSZ   (2 * SUBTILE)          // A, B
#define SMEM_BYTES (2 * BUFSZ)         // 73728, double buffered

__device__ __align__(16) __half g_a[BATCH * NPTS * DIM];  // scaled by 0.5*log2(e)
__device__ __align__(16) __half g_b[BATCH * NPTS * DIM];
__device__ double g_partials[GRID];

__device__ __forceinline__ uint32_t smem_u32(const void* p) {
    uint32_t a;
    asm("{ .reg .u64 t; cvta.to.shared.u64 t, %1; cvt.u32.u64 %0, t; }" : "=r"(a) : "l"(p));
    return a;
}
__device__ __forceinline__ void ldsm4(uint32_t* r, uint32_t addr) {
    asm volatile("ldmatrix.sync.aligned.m8n8.x4.shared.b16 {%0,%1,%2,%3}, [%4];"
                 : "=r"(r[0]), "=r"(r[1]), "=r"(r[2]), "=r"(r[3]) : "r"(addr));
}
__device__ __forceinline__ void mma16816(float* d, const uint32_t* a, const uint32_t* b) {
    asm volatile(
        "mma.sync.aligned.m16n8k16.row.col.f32.f16.f16.f32 "
        "{%0,%1,%2,%3}, {%4,%5,%6,%7}, {%8,%9}, {%0,%1,%2,%3};"
        : "+f"(d[0]), "+f"(d[1]), "+f"(d[2]), "+f"(d[3])
        : "r"(a[0]), "r"(a[1]), "r"(a[2]), "r"(a[3]), "r"(b[0]), "r"(b[1]));
}
__device__ __forceinline__ void cp16(uint32_t dst, const void* src) {
    asm volatile("cp.async.ca.shared.global [%0], [%1], 16;" :: "r"(dst), "l"(src));
}

// ---------------- 1) convert f32 -> fp16 (A pre-scaled by 0.5*log2e) ----------------
__global__ __launch_bounds__(256) void split_kernel(const float* __restrict__ emb) {
    const float C = 0.72134752044448170368f;  // 0.5 * log2(e)
    int i = (blockIdx.x * 256 + threadIdx.x) * 8;
    float4 v0 = *(const float4*)(emb + i);
    float4 v1 = *(const float4*)(emb + i + 4);
    float x[8] = {v0.x, v0.y, v0.z, v0.w, v1.x, v1.y, v1.z, v1.w};
    __half a[8], b[8];
    #pragma unroll
    for (int j = 0; j < 8; ++j) {
        a[j] = __float2half(x[j] * C);
        b[j] = __float2half(x[j]);
    }
    *(uint4*)&g_a[i] = *(uint4*)a;
    *(uint4*)&g_b[i] = *(uint4*)b;
}

// ---------------- 2) persistent HMMA tile kernel ----------------
__device__ __forceinline__ void load_tile(uint32_t sbase, int buf, size_t pbase,
                                          int tn, int tm, int tid) {
    const __half* srcA = g_a + pbase + (size_t)tn * TILE * DIM;
    const __half* srcB = g_b + pbase + (size_t)tm * TILE * DIM;
    const __half* srcs[2] = {srcA, srcB};
    const uint32_t base = sbase + buf * BUFSZ;
    #pragma unroll
    for (int h = 0; h < 2; ++h) {
        const __half* src = srcs[h];
        const uint32_t dst = base + h * SUBTILE;
        #pragma unroll
        for (int it = 0; it < 4; ++it) {
            int q = tid + it * TPB;        // 16B chunk id, 1024 per sub-tile
            int r = q >> 3, c = q & 7;
            cp16(dst + r * SROWB + c * 16, src + r * DIM + c * 8);
        }
    }
    asm volatile("cp.async.commit_group;" ::: "memory");
}

__global__ __launch_bounds__(TPB, 2) void tile_kernel() {
    extern __shared__ __align__(128) char smem[];
    __shared__ double redbuf[8];
    const uint32_t sbase = smem_u32(smem);
    const int tid = threadIdx.x;
    const int wid = tid >> 5;
    const int lid = tid & 31;
    const int wm = wid & 1;            // 2 warps along M (64 rows each)
    const int wn = wid >> 1;           // 4 warps along N (32 cols each)

    const int b    = blockIdx.x & 7;   // fixed batch per CTA
    const int slot = blockIdx.x >> 3;  // 0..36
    const size_t pbase = (size_t)b * NPTS * DIM;

    // Per-lane ldmatrix byte offsets (within a sub-tile), invariant across tiles.
    uint32_t offA[4];
    {
        int row = ((lid >> 3) & 1) * 8 + (lid & 7);
        int kc  = (lid >> 4) * 8;
        #pragma unroll
        for (int ma = 0; ma < 4; ++ma)
            offA[ma] = (uint32_t)((wm * 64 + ma * 16 + row) * SROWB + kc * 2);
    }
    uint32_t offB[2];
    {
        int row = (lid >> 4) * 8 + (lid & 7);
        int kc  = ((lid >> 3) & 1) * 8;
        #pragma unroll
        for (int np = 0; np < 2; ++np)
            offB[np] = (uint32_t)((wn * 32 + np * 16 + row) * SROWB + kc * 2);
    }

    double acc_d = 0.0;                // running per-thread sum across all tiles

    // Decode first tile
    int tt = slot;
    int tn, tm;
    {
        tm = (int)((__fsqrt_rn(8.0f * (float)tt + 1.0f) - 1.0f) * 0.5f);
        while ((tm + 1) * (tm + 2) / 2 <= tt) ++tm;
        while (tm * (tm + 1) / 2 > tt) --tm;
        tn = tt - tm * (tm + 1) / 2;
    }
    if (tt < NTRI) load_tile(sbase, 0, pbase, tn, tm, tid);

    int buf = 0;
    for (; tt < NTRI; ) {
        const int ctn = tn, ctm = tm;
        const int tnext = tt + SLOTS;
        const bool has_next = (tnext < NTRI);
        if (has_next) {
            tm = (int)((__fsqrt_rn(8.0f * (float)tnext + 1.0f) - 1.0f) * 0.5f);
            while ((tm + 1) * (tm + 2) / 2 <= tnext) ++tm;
            while (tm * (tm + 1) / 2 > tnext) --tm;
            tn = tnext - tm * (tm + 1) / 2;
            load_tile(sbase, buf ^ 1, pbase, tn, tm, tid);
            asm volatile("cp.async.wait_group 1;" ::: "memory");
        } else {
            asm volatile("cp.async.wait_group 0;" ::: "memory");
        }
        __syncthreads();               // buf data visible to all warps

        const uint32_t bA = sbase + buf * BUFSZ;
        const uint32_t bB = bA + SUBTILE;

        float acc[4][4][4];
        #pragma unroll
        for (int i = 0; i < 4; ++i)
            #pragma unroll
            for (int j = 0; j < 4; ++j)
                #pragma unroll
                for (int e = 0; e < 4; ++e) acc[i][j][e] = 0.0f;

        #pragma unroll
        for (int ks = 0; ks < 4; ++ks) {
            const uint32_t ko = ks * 32;   // 16 fp16 = 32 B along k
            uint32_t A[4][4], B[2][4];
            #pragma unroll
            for (int ma = 0; ma < 4; ++ma) ldsm4(A[ma], bA + offA[ma] + ko);
            #pragma unroll
            for (int np = 0; np < 2; ++np) ldsm4(B[np], bB + offB[np] + ko);
            #pragma unroll
            for (int ma = 0; ma < 4; ++ma)
                #pragma unroll
                for (int nb = 0; nb < 4; ++nb)
                    mma16816(acc[ma][nb], A[ma], &B[nb >> 1][(nb & 1) * 2]);
        }
        __syncthreads();               // all warps done reading buf -> reusable

        // Epilogue (registers only): sum exp2(acc); weight 2 for off-diag tiles.
        float s[4] = {0.f, 0.f, 0.f, 0.f};
        #pragma unroll
        for (int ma = 0; ma < 4; ++ma)
            #pragma unroll
            for (int nb = 0; nb < 4; ++nb)
                #pragma unroll
                for (int e = 0; e < 4; ++e) {
                    float ex;
                    asm("ex2.approx.f32 %0, %1;" : "=f"(ex) : "f"(acc[ma][nb][e]));
                    s[e] += ex;
                }
        float stot = (s[0] + s[1]) + (s[2] + s[3]);
        acc_d += (ctn == ctm) ? (double)stot : 2.0 * (double)stot;

        buf ^= 1;
        tt = tnext;
    }

    // One block reduction at the very end.
    #pragma unroll
    for (int o = 16; o > 0; o >>= 1)
        acc_d += __shfl_down_sync(0xffffffffu, acc_d, o);
    if (lid == 0) redbuf[wid] = acc_d;
    __syncthreads();
    if (tid == 0) {
        double v = ((redbuf[0] + redbuf[1]) + (redbuf[2] + redbuf[3])) +
                   ((redbuf[4] + redbuf[5]) + (redbuf[6] + redbuf[7]));
        g_partials[blockIdx.x] = v;
    }
}

// ---------------- 3) finalize: warp-per-batch logsumexp mean ----------------
__global__ __launch_bounds__(256) void fin_kernel(float* __restrict__ out) {
    const int tid = threadIdx.x;
    const int w = tid >> 5, lid = tid & 31;   // warp w handles batch w
    __shared__ double logs[8];
    double s = 0.0;
    for (int i = lid; i < SLOTS; i += 32)
        s += g_partials[(i << 3) + w];        // CTA index = slot*8 + batch
    #pragma unroll
    for (int o = 16; o > 0; o >>= 1)
        s += __shfl_down_sync(0xffffffffu, s, o);
    if (lid == 0) logs[w] = log(s);
    __syncthreads();
    if (tid == 0) {
        double L = 0.0;
        #pragma unroll
        for (int i = 0; i < 8; ++i) L += logs[i];
        *out = (float)(L / 8.0);
    }
}

extern "C" void kernel_launch(void* const* d_in, const int* in_sizes, int n_in,
                              void* d_out, int out_size) {
    (void)in_sizes; (void)n_in; (void)out_size;
    const float* emb = (const float*)d_in[0];
    float* out = (float*)d_out;
    cudaFuncSetAttribute(tile_kernel, cudaFuncAttributeMaxDynamicSharedMemorySize, SMEM_BYTES);
    split_kernel<<<BATCH * NPTS * DIM / (256 * 8), 256>>>(emb);
    tile_kernel<<<GRID, TPB, SMEM_BYTES>>>();
    fin_kernel<<<1, 256>>>(out);
}

// round 8
// speedup vs baseline: 1.0029x; 1.0029x over previous
#include <cuda_runtime.h>
#include <cuda_fp16.h>
#include <math.h>
#include <stdint.h>

#define BATCH 8
#define NPTS  4096
#define DIM   64
#define TILE  128
#define NT    (NPTS / TILE)            // 32
#define NTRI  (NT * (NT + 1) / 2)      // 528 upper-tri tiles per batch
#define SLOTS 37                       // CTAs per batch
#define GRID  (BATCH * SLOTS)          // 296
#define TPB   256

// smem sub-tile: 128 rows x 72 fp16 (144 B stride) -> conflict-free ldmatrix
#define SROWB   144
#define SUBTILE (128 * SROWB)          // 18432 B
#define BUFSZ   (2 * SUBTILE)          // A, B
#define SMEM_BYTES (2 * BUFSZ)         // 73728, double buffered

__device__ __align__(16) __half g_a[BATCH * NPTS * DIM];  // scaled by 0.5*log2(e)
__device__ __align__(16) __half g_b[BATCH * NPTS * DIM];
__device__ double g_partials[GRID];
__device__ unsigned g_cnt = 0;

__device__ __forceinline__ uint32_t smem_u32(const void* p) {
    uint32_t a;
    asm("{ .reg .u64 t; cvta.to.shared.u64 t, %1; cvt.u32.u64 %0, t; }" : "=r"(a) : "l"(p));
    return a;
}
__device__ __forceinline__ void ldsm4(uint32_t* r, uint32_t addr) {
    asm volatile("ldmatrix.sync.aligned.m8n8.x4.shared.b16 {%0,%1,%2,%3}, [%4];"
                 : "=r"(r[0]), "=r"(r[1]), "=r"(r[2]), "=r"(r[3]) : "r"(addr));
}
__device__ __forceinline__ void mma16816(float* d, const uint32_t* a, const uint32_t* b) {
    asm volatile(
        "mma.sync.aligned.m16n8k16.row.col.f32.f16.f16.f32 "
        "{%0,%1,%2,%3}, {%4,%5,%6,%7}, {%8,%9}, {%0,%1,%2,%3};"
        : "+f"(d[0]), "+f"(d[1]), "+f"(d[2]), "+f"(d[3])
        : "r"(a[0]), "r"(a[1]), "r"(a[2]), "r"(a[3]), "r"(b[0]), "r"(b[1]));
}
__device__ __forceinline__ void cp16(uint32_t dst, const void* src) {
    asm volatile("cp.async.ca.shared.global [%0], [%1], 16;" :: "r"(dst), "l"(src));
}
// ex2 is non-volatile on purpose: ptxas may schedule it into the MMA stream.
__device__ __forceinline__ float ex2f(float x) {
    float e;
    asm("ex2.approx.f32 %0, %1;" : "=f"(e) : "f"(x));
    return e;
}

// ---------------- 1) convert f32 -> fp16 (A pre-scaled by 0.5*log2e) ----------------
__global__ __launch_bounds__(256) void split_kernel(const float* __restrict__ emb) {
    const float C = 0.72134752044448170368f;  // 0.5 * log2(e)
    int i = (blockIdx.x * 256 + threadIdx.x) * 4;
    float4 v = *(const float4*)(emb + i);
    float x[4] = {v.x, v.y, v.z, v.w};
    __half a[4], b[4];
    #pragma unroll
    for (int j = 0; j < 4; ++j) {
        a[j] = __float2half(x[j] * C);
        b[j] = __float2half(x[j]);
    }
    *(uint2*)&g_a[i] = *(uint2*)a;
    *(uint2*)&g_b[i] = *(uint2*)b;
}

// ---------------- 2) persistent HMMA tile kernel (fused finalize) ----------------
__device__ __forceinline__ void load_tile(uint32_t sbase, int buf, size_t pbase,
                                          int tn, int tm, int tid) {
    const __half* srcA = g_a + pbase + (size_t)tn * TILE * DIM;
    const __half* srcB = g_b + pbase + (size_t)tm * TILE * DIM;
    const __half* srcs[2] = {srcA, srcB};
    const uint32_t base = sbase + buf * BUFSZ;
    #pragma unroll
    for (int h = 0; h < 2; ++h) {
        const __half* src = srcs[h];
        const uint32_t dst = base + h * SUBTILE;
        #pragma unroll
        for (int it = 0; it < 4; ++it) {
            int q = tid + it * TPB;        // 16B chunk id, 1024 per sub-tile
            int r = q >> 3, c = q & 7;
            cp16(dst + r * SROWB + c * 16, src + r * DIM + c * 8);
        }
    }
    asm volatile("cp.async.commit_group;" ::: "memory");
}

__global__ __launch_bounds__(TPB, 2) void tile_kernel(float* __restrict__ out) {
    extern __shared__ __align__(128) char smem[];
    __shared__ double redbuf[8];
    __shared__ int is_last_s;
    const uint32_t sbase = smem_u32(smem);
    const int tid = threadIdx.x;
    const int wid = tid >> 5;
    const int lid = tid & 31;
    const int wm = wid & 1;            // 2 warps along M (64 rows each)
    const int wn = wid >> 1;           // 4 warps along N (32 cols each)

    const int b    = blockIdx.x & 7;   // fixed batch per CTA
    const int slot = blockIdx.x >> 3;  // 0..36
    const size_t pbase = (size_t)b * NPTS * DIM;

    // Per-lane ldmatrix byte offsets (within a sub-tile), invariant across tiles.
    uint32_t offA[4];
    {
        int row = ((lid >> 3) & 1) * 8 + (lid & 7);
        int kc  = (lid >> 4) * 8;
        #pragma unroll
        for (int ma = 0; ma < 4; ++ma)
            offA[ma] = (uint32_t)((wm * 64 + ma * 16 + row) * SROWB + kc * 2);
    }
    uint32_t offB[2];
    {
        int row = (lid >> 4) * 8 + (lid & 7);
        int kc  = ((lid >> 3) & 1) * 8;
        #pragma unroll
        for (int np = 0; np < 2; ++np)
            offB[np] = (uint32_t)((wn * 32 + np * 16 + row) * SROWB + kc * 2);
    }

    double acc_d = 0.0;                // running per-thread sum across all tiles
    float  pw    = 0.0f;               // weight of PENDING (previous) tile; 0 = none
    float acc[4][4][4];
    #pragma unroll
    for (int i = 0; i < 4; ++i)
        #pragma unroll
        for (int j = 0; j < 4; ++j)
            #pragma unroll
            for (int e = 0; e < 4; ++e) acc[i][j][e] = 0.0f;

    // Decode first tile
    int tt = slot;
    int tn, tm;
    {
        tm = (int)((__fsqrt_rn(8.0f * (float)tt + 1.0f) - 1.0f) * 0.5f);
        while ((tm + 1) * (tm + 2) / 2 <= tt) ++tm;
        while (tm * (tm + 1) / 2 > tt) --tm;
        tn = tt - tm * (tm + 1) / 2;
    }
    load_tile(sbase, 0, pbase, tn, tm, tid);

    int buf = 0;
    for (; tt < NTRI; ) {
        const int ctn = tn, ctm = tm;
        const int tnext = tt + SLOTS;
        const bool has_next = (tnext < NTRI);
        if (has_next) {
            tm = (int)((__fsqrt_rn(8.0f * (float)tnext + 1.0f) - 1.0f) * 0.5f);
            while ((tm + 1) * (tm + 2) / 2 <= tnext) ++tm;
            while (tm * (tm + 1) / 2 > tnext) --tm;
            tn = tnext - tm * (tm + 1) / 2;
            load_tile(sbase, buf ^ 1, pbase, tn, tm, tid);
            asm volatile("cp.async.wait_group 1;" ::: "memory");
        } else {
            asm volatile("cp.async.wait_group 0;" ::: "memory");
        }
        __syncthreads();               // buf data visible to all warps

        const uint32_t bA = sbase + buf * BUFSZ;
        const uint32_t bB = bA + SUBTILE;

        // Pipelined epilogue of the PREVIOUS tile: ex2 (non-volatile) can be
        // interleaved by ptxas with the MMA stream below; each ex2 only needs
        // to precede the first mma write of its own accumulator chain.
        float s0 = 0.f, s1 = 0.f, s2 = 0.f, s3 = 0.f;
        #pragma unroll
        for (int ma = 0; ma < 4; ++ma)
            #pragma unroll
            for (int nb = 0; nb < 4; ++nb) {
                s0 += ex2f(acc[ma][nb][0]);
                s1 += ex2f(acc[ma][nb][1]);
                s2 += ex2f(acc[ma][nb][2]);
                s3 += ex2f(acc[ma][nb][3]);
                acc[ma][nb][0] = 0.f; acc[ma][nb][1] = 0.f;
                acc[ma][nb][2] = 0.f; acc[ma][nb][3] = 0.f;
            }
        acc_d += (double)pw * (double)((s0 + s1) + (s2 + s3));  // pw=0 first iter

        #pragma unroll
        for (int ks = 0; ks < 4; ++ks) {
            const uint32_t ko = ks * 32;   // 16 fp16 = 32 B along k
            uint32_t A[4][4], B[2][4];
            #pragma unroll
            for (int ma = 0; ma < 4; ++ma) ldsm4(A[ma], bA + offA[ma] + ko);
            #pragma unroll
            for (int np = 0; np < 2; ++np) ldsm4(B[np], bB + offB[np] + ko);
            #pragma unroll
            for (int ma = 0; ma < 4; ++ma)
                #pragma unroll
                for (int nb = 0; nb < 4; ++nb)
                    mma16816(acc[ma][nb], A[ma], &B[nb >> 1][(nb & 1) * 2]);
        }
        __syncthreads();               // all warps done reading buf -> reusable

        pw = (ctn == ctm) ? 1.0f : 2.0f;
        buf ^= 1;
        tt = tnext;
    }

    // Final pending epilogue.
    {
        float s0 = 0.f, s1 = 0.f, s2 = 0.f, s3 = 0.f;
        #pragma unroll
        for (int ma = 0; ma < 4; ++ma)
            #pragma unroll
            for (int nb = 0; nb < 4; ++nb) {
                s0 += ex2f(acc[ma][nb][0]);
                s1 += ex2f(acc[ma][nb][1]);
                s2 += ex2f(acc[ma][nb][2]);
                s3 += ex2f(acc[ma][nb][3]);
            }
        acc_d += (double)pw * (double)((s0 + s1) + (s2 + s3));
    }

    // One block reduction at the very end.
    #pragma unroll
    for (int o = 16; o > 0; o >>= 1)
        acc_d += __shfl_down_sync(0xffffffffu, acc_d, o);
    if (lid == 0) redbuf[wid] = acc_d;
    __syncthreads();
    if (tid == 0) {
        double v = ((redbuf[0] + redbuf[1]) + (redbuf[2] + redbuf[3])) +
                   ((redbuf[4] + redbuf[5]) + (redbuf[6] + redbuf[7]));
        g_partials[blockIdx.x] = v;
    }

    // Fused finalize: last CTA to arrive reduces per-batch and writes the loss.
    __threadfence();
    if (tid == 0) {
        unsigned o = atomicAdd(&g_cnt, 1u);
        is_last_s = (o == GRID - 1) ? 1 : 0;
    }
    __syncthreads();
    if (is_last_s) {
        __threadfence();
        const int w = wid;             // warp w handles batch w
        double s = 0.0;
        for (int i = lid; i < SLOTS; i += 32)
            s += g_partials[(i << 3) + w];
        #pragma unroll
        for (int o = 16; o > 0; o >>= 1)
            s += __shfl_down_sync(0xffffffffu, s, o);
        if (lid == 0) redbuf[w] = log(s);
        __syncthreads();
        if (tid == 0) {
            double L = ((redbuf[0] + redbuf[1]) + (redbuf[2] + redbuf[3])) +
                       ((redbuf[4] + redbuf[5]) + (redbuf[6] + redbuf[7]));
            *out = (float)(L / 8.0);
            g_cnt = 0;                 // reset for next graph replay
        }
    }
}

extern "C" void kernel_launch(void* const* d_in, const int* in_sizes, int n_in,
                              void* d_out, int out_size) {
    (void)in_sizes; (void)n_in; (void)out_size;
    const float* emb = (const float*)d_in[0];
    float* out = (float*)d_out;
    cudaFuncSetAttribute(tile_kernel, cudaFuncAttributeMaxDynamicSharedMemorySize, SMEM_BYTES);
    split_kernel<<<BATCH * NPTS * DIM / (256 * 4), 256>>>(emb);
    tile_kernel<<<GRID, TPB, SMEM_BYTES>>>(out);
}

// round 10
// speedup vs baseline: 1.3918x; 1.3878x over previous
#include <cuda_runtime.h>
#include <cuda_fp16.h>
#include <math.h>
#include <stdint.h>

#define BATCH 8
#define NPTS  4096
#define DIM   64
#define TILE  128
#define NT    (NPTS / TILE)            // 32
#define NTRI  (NT * (NT + 1) / 2)      // 528 upper-tri tiles per batch
#define SLOTS 37                       // CTAs per batch
#define GRID  (BATCH * SLOTS)          // 296
#define TPB   256

// smem sub-tile: 128 rows x 72 fp16 (144 B stride) -> conflict-free ldmatrix/STS
#define SROWB   144
#define SUBTILE (128 * SROWB)          // 18432 B
#define BUFSZ   (2 * SUBTILE)          // A+B = 36864 B
#define NBUF    3                      // triple buffer -> single barrier per tile
#define SMEM_BYTES (NBUF * BUFSZ)      // 110592 (2 CTAs/SM fit)

__device__ __align__(16) __half g_a[BATCH * NPTS * DIM];  // scaled by 0.5*log2(e)
__device__ __align__(16) __half g_b[BATCH * NPTS * DIM];
__device__ double g_partials[GRID];
__device__ unsigned g_cnt = 0;

__device__ __forceinline__ uint32_t smem_u32(const void* p) {
    uint32_t a;
    asm("{ .reg .u64 t; cvta.to.shared.u64 t, %1; cvt.u32.u64 %0, t; }" : "=r"(a) : "l"(p));
    return a;
}
template <int IMM>
__device__ __forceinline__ void ldsm4i(uint32_t* r, uint32_t addr) {
    asm volatile("ldmatrix.sync.aligned.m8n8.x4.shared.b16 {%0,%1,%2,%3}, [%4+%5];"
                 : "=r"(r[0]), "=r"(r[1]), "=r"(r[2]), "=r"(r[3])
                 : "r"(addr), "n"(IMM));
}
__device__ __forceinline__ void mma_acc(float* d, const uint32_t* a, const uint32_t* b) {
    asm volatile(
        "mma.sync.aligned.m16n8k16.row.col.f32.f16.f16.f32 "
        "{%0,%1,%2,%3}, {%4,%5,%6,%7}, {%8,%9}, {%0,%1,%2,%3};"
        : "+f"(d[0]), "+f"(d[1]), "+f"(d[2]), "+f"(d[3])
        : "r"(a[0]), "r"(a[1]), "r"(a[2]), "r"(a[3]), "r"(b[0]), "r"(b[1]));
}
// ks0 variant: C = 0 -> writes acc fresh, no zeroing MOVs needed.
__device__ __forceinline__ void mma_zro(float* d, const uint32_t* a, const uint32_t* b) {
    asm volatile(
        "mma.sync.aligned.m16n8k16.row.col.f32.f16.f16.f32 "
        "{%0,%1,%2,%3}, {%4,%5,%6,%7}, {%8,%9}, {%10,%10,%10,%10};"
        : "=f"(d[0]), "=f"(d[1]), "=f"(d[2]), "=f"(d[3])
        : "r"(a[0]), "r"(a[1]), "r"(a[2]), "r"(a[3]), "r"(b[0]), "r"(b[1]), "f"(0.0f));
}
template <int DI, int SI>
__device__ __forceinline__ void cp16i(uint32_t dst, const __half* src) {
    asm volatile("cp.async.ca.shared.global [%0+%2], [%1+%3], 16;"
                 :: "r"(dst), "l"(src), "n"(DI), "n"(SI));
}
__device__ __forceinline__ float ex2f(float x) {
    float e;
    asm("ex2.approx.f32 %0, %1;" : "=f"(e) : "f"(x));
    return e;
}

// ---------------- 1) convert f32 -> fp16 (A pre-scaled by 0.5*log2e) ----------------
__global__ __launch_bounds__(256) void split_kernel(const float* __restrict__ emb) {
    const float C = 0.72134752044448170368f;  // 0.5 * log2(e)
    int i = (blockIdx.x * 256 + threadIdx.x) * 4;
    float4 v = *(const float4*)(emb + i);
    float x[4] = {v.x, v.y, v.z, v.w};
    __half a[4], b[4];
    #pragma unroll
    for (int j = 0; j < 4; ++j) {
        a[j] = __float2half(x[j] * C);
        b[j] = __float2half(x[j]);
    }
    *(uint2*)&g_a[i] = *(uint2*)a;
    *(uint2*)&g_b[i] = *(uint2*)b;
}

// ---------------- 2) persistent HMMA tile kernel (fused finalize) ----------------
// Per-thread: loads rows r0, r0+32, r0+64, r0+96 at fixed 16B col -> imm offsets.
__device__ __forceinline__ void load_tile(uint32_t dstA, const __half* sA, const __half* sB) {
    cp16i<0 * SROWB, 0 * DIM * 2>(dstA, sA);
    cp16i<32 * SROWB, 32 * DIM * 2>(dstA, sA);
    cp16i<64 * SROWB, 64 * DIM * 2>(dstA, sA);
    cp16i<96 * SROWB, 96 * DIM * 2>(dstA, sA);
    cp16i<SUBTILE + 0 * SROWB, 0 * DIM * 2>(dstA, sB);
    cp16i<SUBTILE + 32 * SROWB, 32 * DIM * 2>(dstA, sB);
    cp16i<SUBTILE + 64 * SROWB, 64 * DIM * 2>(dstA, sB);
    cp16i<SUBTILE + 96 * SROWB, 96 * DIM * 2>(dstA, sB);
    asm volatile("cp.async.commit_group;" ::: "memory");
}

#define KSTEP(KO, MMAFN)                                                          \
    {                                                                             \
        uint32_t A[4][4], B[2][4];                                                \
        ldsm4i<KO>(A[0], aA0); ldsm4i<KO>(A[1], aA1);                             \
        ldsm4i<KO>(A[2], aA2); ldsm4i<KO>(A[3], aA3);                             \
        ldsm4i<KO>(B[0], aB0); ldsm4i<KO>(B[1], aB1);                             \
        _Pragma("unroll")                                                         \
        for (int ma = 0; ma < 4; ++ma)                                            \
            _Pragma("unroll")                                                     \
            for (int nb = 0; nb < 4; ++nb)                                        \
                MMAFN(acc[ma][nb], A[ma], &B[nb >> 1][(nb & 1) * 2]);             \
    }

__global__ __launch_bounds__(TPB, 2) void tile_kernel(float* __restrict__ out) {
    extern __shared__ __align__(128) char smem[];
    __shared__ double redbuf[8];
    __shared__ int is_last_s;
    const uint32_t sbase = smem_u32(smem);
    const int tid = threadIdx.x;
    const int wid = tid >> 5;
    const int lid = tid & 31;
    const int wm = wid & 1;            // 2 warps along M (64 rows each)
    const int wn = wid >> 1;           // 4 warps along N (32 cols each)

    const int bb   = blockIdx.x & 7;   // fixed batch per CTA
    const int slot = blockIdx.x >> 3;  // 0..36
    const __half* gA = g_a + (size_t)bb * NPTS * DIM;
    const __half* gB = g_b + (size_t)bb * NPTS * DIM;

    // Per-thread load offsets (elements / bytes), invariant across tiles.
    const int srcoff = (tid >> 3) * DIM + (tid & 7) * 8;                 // elements
    const uint32_t dsto = (uint32_t)((tid >> 3) * SROWB + (tid & 7) * 16);

    // Per-lane ldmatrix byte offsets within a buffer, invariant across tiles.
    uint32_t offA[4];
    {
        int row = ((lid >> 3) & 1) * 8 + (lid & 7);
        int kc  = (lid >> 4) * 8;
        #pragma unroll
        for (int ma = 0; ma < 4; ++ma)
            offA[ma] = (uint32_t)((wm * 64 + ma * 16 + row) * SROWB + kc * 2);
    }
    uint32_t offB[2];
    {
        int row = (lid >> 4) * 8 + (lid & 7);
        int kc  = ((lid >> 3) & 1) * 8;
        #pragma unroll
        for (int np = 0; np < 2; ++np)
            offB[np] = (uint32_t)(SUBTILE + (wn * 32 + np * 16 + row) * SROWB + kc * 2);
    }

    float facc = 0.0f;                 // running per-thread sum (all positive)
    float pw   = 0.0f;                 // weight of pending (previous) tile; 0 = none
    float acc[4][4][4];
    #pragma unroll
    for (int i = 0; i < 4; ++i)
        #pragma unroll
        for (int j = 0; j < 4; ++j)
            #pragma unroll
            for (int e = 0; e < 4; ++e) acc[i][j][e] = 0.0f;

    // Incremental triangular decode: tt = tm(tm+1)/2 + tn, 0 <= tn <= tm.
    int tn = slot, tm = 0;
    while (tn > tm) { tn -= (tm + 1); ++tm; }

    load_tile(sbase + dsto, gA + tn * (TILE * DIM) + srcoff,
              gB + tm * (TILE * DIM) + srcoff);

    int buf = 0;
    for (int tt = slot; tt < NTRI; tt += SLOTS) {
        const int diag = (tn == tm);
        const int nbuf = (buf == NBUF - 1) ? 0 : buf + 1;
        if (tt + SLOTS < NTRI) {
            tn += SLOTS;
            while (tn > tm) { tn -= (tm + 1); ++tm; }
            load_tile(sbase + nbuf * BUFSZ + dsto,
                      gA + tn * (TILE * DIM) + srcoff,
                      gB + tm * (TILE * DIM) + srcoff);
            asm volatile("cp.async.wait_group 1;" ::: "memory");
        } else {
            asm volatile("cp.async.wait_group 0;" ::: "memory");
        }
        __syncthreads();               // single barrier: data ready; WAR safe at depth 3

        const uint32_t bufbase = sbase + buf * BUFSZ;
        const uint32_t aA0 = bufbase + offA[0], aA1 = bufbase + offA[1];
        const uint32_t aA2 = bufbase + offA[2], aA3 = bufbase + offA[3];
        const uint32_t aB0 = bufbase + offB[0], aB1 = bufbase + offB[1];

        // Epilogue of PREVIOUS tile (pw=0 on first iter; acc initialized to 0).
        {
            float s0 = 0.f, s1 = 0.f, s2 = 0.f, s3 = 0.f;
            #pragma unroll
            for (int ma = 0; ma < 4; ++ma)
                #pragma unroll
                for (int nb = 0; nb < 4; ++nb) {
                    s0 += ex2f(acc[ma][nb][0]);
                    s1 += ex2f(acc[ma][nb][1]);
                    s2 += ex2f(acc[ma][nb][2]);
                    s3 += ex2f(acc[ma][nb][3]);
                }
            facc += pw * ((s0 + s1) + (s2 + s3));
        }

        KSTEP(0,  mma_zro)             // ks0 writes acc fresh
        KSTEP(32, mma_acc)
        KSTEP(64, mma_acc)
        KSTEP(96, mma_acc)

        pw = diag ? 1.0f : 2.0f;
        buf = nbuf;
    }

    // Final pending epilogue.
    {
        float s0 = 0.f, s1 = 0.f, s2 = 0.f, s3 = 0.f;
        #pragma unroll
        for (int ma = 0; ma < 4; ++ma)
            #pragma unroll
            for (int nb = 0; nb < 4; ++nb) {
                s0 += ex2f(acc[ma][nb][0]);
                s1 += ex2f(acc[ma][nb][1]);
                s2 += ex2f(acc[ma][nb][2]);
                s3 += ex2f(acc[ma][nb][3]);
            }
        facc += pw * ((s0 + s1) + (s2 + s3));
    }

    // One block reduction in double at the very end.
    double acc_d = (double)facc;
    #pragma unroll
    for (int o = 16; o > 0; o >>= 1)
        acc_d += __shfl_down_sync(0xffffffffu, acc_d, o);
    if (lid == 0) redbuf[wid] = acc_d;
    __syncthreads();
    if (tid == 0) {
        double v = ((redbuf[0] + redbuf[1]) + (redbuf[2] + redbuf[3])) +
                   ((redbuf[4] + redbuf[5]) + (redbuf[6] + redbuf[7]));
        g_partials[blockIdx.x] = v;
    }

    // Fused finalize: last CTA reduces per-batch and writes the loss.
    __threadfence();
    if (tid == 0) {
        unsigned o = atomicAdd(&g_cnt, 1u);
        is_last_s = (o == GRID - 1) ? 1 : 0;
    }
    __syncthreads();
    if (is_last_s) {
        __threadfence();
        const int w = wid;             // warp w handles batch w
        double s = 0.0;
        for (int i = lid; i < SLOTS; i += 32)
            s += g_partials[(i << 3) + w];
        #pragma unroll
        for (int o = 16; o > 0; o >>= 1)
            s += __shfl_down_sync(0xffffffffu, s, o);
        if (lid == 0) redbuf[w] = log(s);
        __syncthreads();
        if (tid == 0) {
            double L = ((redbuf[0] + redbuf[1]) + (redbuf[2] + redbuf[3])) +
                       ((redbuf[4] + redbuf[5]) + (redbuf[6] + redbuf[7]));
            *out = (float)(L / 8.0);
            g_cnt = 0;                 // reset for next graph replay
        }
    }
}

extern "C" void kernel_launch(void* const* d_in, const int* in_sizes, int n_in,
                              void* d_out, int out_size) {
    (void)in_sizes; (void)n_in; (void)out_size;
    const float* emb = (const float*)d_in[0];
    float* out = (float*)d_out;
    cudaFuncSetAttribute(tile_kernel, cudaFuncAttributeMaxDynamicSharedMemorySize, SMEM_BYTES);
    split_kernel<<<BATCH * NPTS * DIM / (256 * 4), 256>>>(emb);
    tile_kernel<<<GRID, TPB, SMEM_BYTES>>>(out);
}

// round 11
// speedup vs baseline: 1.4372x; 1.0326x over previous
#include <cuda_runtime.h>
#include <cuda_fp16.h>
#include <math.h>
#include <stdint.h>

#define BATCH 8
#define NPTS  4096
#define DIM   64
#define TILE  128
#define NT    (NPTS / TILE)            // 32
#define NTRI  (NT * (NT + 1) / 2)      // 528 upper-tri tiles per batch
#define SLOTS 37                       // CTAs per batch
#define GRID  (BATCH * SLOTS)          // 296
#define TPB   256

// smem sub-tile: 128 rows x 72 fp16 (144 B stride) -> conflict-free ldmatrix/STS
#define SROWB   144
#define SUBTILE (128 * SROWB)          // 18432 B
#define BUFSZ   (2 * SUBTILE)          // A+B = 36864 B
#define NBUF    3                      // triple buffer -> single barrier per tile
#define SMEM_BYTES (NBUF * BUFSZ)      // 110592 (2 CTAs/SM)

// Both operands from ONE array scaled by sqrt(0.5*log2(e)):
// (s*a)·(s*b) = 0.5*log2(e)*a·b  ->  ex2(acc) = exp(0.5*<a,b>)
__device__ __align__(16) __half g_s[BATCH * NPTS * DIM];
__device__ double g_partials[GRID];
__device__ unsigned g_cnt = 0;

__device__ __forceinline__ uint32_t smem_u32(const void* p) {
    uint32_t a;
    asm("{ .reg .u64 t; cvta.to.shared.u64 t, %1; cvt.u32.u64 %0, t; }" : "=r"(a) : "l"(p));
    return a;
}
template <int IMM>
__device__ __forceinline__ void ldsm4i(uint32_t* r, uint32_t addr) {
    asm volatile("ldmatrix.sync.aligned.m8n8.x4.shared.b16 {%0,%1,%2,%3}, [%4+%5];"
                 : "=r"(r[0]), "=r"(r[1]), "=r"(r[2]), "=r"(r[3])
                 : "r"(addr), "n"(IMM));
}
// NON-volatile MMA: ordering is fully pinned by register dependencies
// (reads ldsm outputs, chains through acc). Lets ptxas interleave with MUFU.
__device__ __forceinline__ void mma_acc(float* d, const uint32_t* a, const uint32_t* b) {
    asm("mma.sync.aligned.m16n8k16.row.col.f32.f16.f16.f32 "
        "{%0,%1,%2,%3}, {%4,%5,%6,%7}, {%8,%9}, {%0,%1,%2,%3};"
        : "+f"(d[0]), "+f"(d[1]), "+f"(d[2]), "+f"(d[3])
        : "r"(a[0]), "r"(a[1]), "r"(a[2]), "r"(a[3]), "r"(b[0]), "r"(b[1]));
}
// ks0 variant: C = 0 -> writes acc fresh, no zeroing MOVs needed.
__device__ __forceinline__ void mma_zro(float* d, const uint32_t* a, const uint32_t* b) {
    asm("mma.sync.aligned.m16n8k16.row.col.f32.f16.f16.f32 "
        "{%0,%1,%2,%3}, {%4,%5,%6,%7}, {%8,%9}, {%10,%10,%10,%10};"
        : "=f"(d[0]), "=f"(d[1]), "=f"(d[2]), "=f"(d[3])
        : "r"(a[0]), "r"(a[1]), "r"(a[2]), "r"(a[3]), "r"(b[0]), "r"(b[1]), "f"(0.0f));
}
template <int DI, int SI>
__device__ __forceinline__ void cp16i(uint32_t dst, const __half* src) {
    asm volatile("cp.async.ca.shared.global [%0+%2], [%1+%3], 16;"
                 :: "r"(dst), "l"(src), "n"(DI), "n"(SI));
}
__device__ __forceinline__ float ex2f(float x) {
    float e;
    asm("ex2.approx.f32 %0, %1;" : "=f"(e) : "f"(x));
    return e;
}

// ---------------- 1) convert f32 -> fp16 scaled by sqrt(0.5*log2e) ----------------
__global__ __launch_bounds__(256) void split_kernel(const float* __restrict__ emb) {
    const float SQC = 0.84932180612318867f;  // sqrt(0.5*log2(e))
    int i = (blockIdx.x * 256 + threadIdx.x) * 4;
    float4 v = *(const float4*)(emb + i);
    float x[4] = {v.x, v.y, v.z, v.w};
    __half s[4];
    #pragma unroll
    for (int j = 0; j < 4; ++j) s[j] = __float2half(x[j] * SQC);
    *(uint2*)&g_s[i] = *(uint2*)s;
}

// ---------------- 2) persistent HMMA tile kernel (fused finalize) ----------------
__device__ __forceinline__ void load_tile(uint32_t dstA, const __half* sA, const __half* sB,
                                          bool dg) {
    cp16i<0 * SROWB, 0 * DIM * 2>(dstA, sA);
    cp16i<32 * SROWB, 32 * DIM * 2>(dstA, sA);
    cp16i<64 * SROWB, 64 * DIM * 2>(dstA, sA);
    cp16i<96 * SROWB, 96 * DIM * 2>(dstA, sA);
    if (!dg) {   // diagonal tile: B region = A region, skip the B load
        cp16i<SUBTILE + 0 * SROWB, 0 * DIM * 2>(dstA, sB);
        cp16i<SUBTILE + 32 * SROWB, 32 * DIM * 2>(dstA, sB);
        cp16i<SUBTILE + 64 * SROWB, 64 * DIM * 2>(dstA, sB);
        cp16i<SUBTILE + 96 * SROWB, 96 * DIM * 2>(dstA, sB);
    }
    asm volatile("cp.async.commit_group;" ::: "memory");
}

#define KSTEP(KO)                                                                 \
    {                                                                             \
        uint32_t A[4][4], B[2][4];                                                \
        ldsm4i<KO>(A[0], aA0); ldsm4i<KO>(A[1], aA1);                             \
        ldsm4i<KO>(A[2], aA2); ldsm4i<KO>(A[3], aA3);                             \
        ldsm4i<KO>(B[0], aB0); ldsm4i<KO>(B[1], aB1);                             \
        _Pragma("unroll")                                                         \
        for (int ma = 0; ma < 4; ++ma)                                            \
            _Pragma("unroll")                                                     \
            for (int nb = 0; nb < 4; ++nb)                                        \
                mma_acc(acc[ma][nb], A[ma], &B[nb >> 1][(nb & 1) * 2]);           \
    }

__global__ __launch_bounds__(TPB, 2) void tile_kernel(float* __restrict__ out) {
    extern __shared__ __align__(128) char smem[];
    __shared__ double redbuf[8];
    __shared__ int is_last_s;
    const uint32_t sbase = smem_u32(smem);
    const int tid = threadIdx.x;
    const int wid = tid >> 5;
    const int lid = tid & 31;
    const int wm = wid & 1;            // 2 warps along M (64 rows each)
    const int wn = wid >> 1;           // 4 warps along N (32 cols each)

    const int bb   = blockIdx.x & 7;   // fixed batch per CTA
    const int slot = blockIdx.x >> 3;  // 0..36
    const __half* gS = g_s + (size_t)bb * NPTS * DIM;

    const int srcoff = (tid >> 3) * DIM + (tid & 7) * 8;                 // elements
    const uint32_t dsto = (uint32_t)((tid >> 3) * SROWB + (tid & 7) * 16);

    uint32_t offA[4];
    {
        int row = ((lid >> 3) & 1) * 8 + (lid & 7);
        int kc  = (lid >> 4) * 8;
        #pragma unroll
        for (int ma = 0; ma < 4; ++ma)
            offA[ma] = (uint32_t)((wm * 64 + ma * 16 + row) * SROWB + kc * 2);
    }
    uint32_t offB[2];   // WITHOUT the SUBTILE base (added per tile; diag -> A region)
    {
        int row = (lid >> 4) * 8 + (lid & 7);
        int kc  = ((lid >> 3) & 1) * 8;
        #pragma unroll
        for (int np = 0; np < 2; ++np)
            offB[np] = (uint32_t)((wn * 32 + np * 16 + row) * SROWB + kc * 2);
    }

    float facc = 0.0f;                 // running per-thread sum (all positive)
    float pw   = 0.0f;                 // weight of pending (previous) tile; 0 = none
    float acc[4][4][4];
    #pragma unroll
    for (int i = 0; i < 4; ++i)
        #pragma unroll
        for (int j = 0; j < 4; ++j)
            #pragma unroll
            for (int e = 0; e < 4; ++e) acc[i][j][e] = 0.0f;

    // Incremental triangular decode: tt = tm(tm+1)/2 + tn, 0 <= tn <= tm.
    int tn = slot, tm = 0;
    while (tn > tm) { tn -= (tm + 1); ++tm; }

    load_tile(sbase + dsto, gS + tn * (TILE * DIM) + srcoff,
              gS + tm * (TILE * DIM) + srcoff, tn == tm);

    int buf = 0;
    for (int tt = slot; tt < NTRI; tt += SLOTS) {
        const int cdiag = (tn == tm);
        const int nbuf = (buf == NBUF - 1) ? 0 : buf + 1;
        if (tt + SLOTS < NTRI) {
            tn += SLOTS;
            while (tn > tm) { tn -= (tm + 1); ++tm; }
            load_tile(sbase + nbuf * BUFSZ + dsto,
                      gS + tn * (TILE * DIM) + srcoff,
                      gS + tm * (TILE * DIM) + srcoff, tn == tm);
            asm volatile("cp.async.wait_group 1;" ::: "memory");
        } else {
            asm volatile("cp.async.wait_group 0;" ::: "memory");
        }
        __syncthreads();               // single barrier: data ready; WAR safe at depth 3

        const uint32_t bufbase = sbase + buf * BUFSZ;
        const uint32_t aA0 = bufbase + offA[0], aA1 = bufbase + offA[1];
        const uint32_t aA2 = bufbase + offA[2], aA3 = bufbase + offA[3];
        const uint32_t bB  = bufbase + (cdiag ? 0u : (uint32_t)SUBTILE);
        const uint32_t aB0 = bB + offB[0], aB1 = bB + offB[1];

        float s0 = 0.f, s1 = 0.f, s2 = 0.f, s3 = 0.f;

        // kstep 0 interleaved with the previous tile's epilogue:
        // epilogue chunk for acc[ma] precedes the mma_zro that overwrites it,
        // so MUFU ex2s schedule into the HMMA shadow.
        {
            uint32_t A[4][4], B[2][4];
            ldsm4i<0>(A[0], aA0); ldsm4i<0>(A[1], aA1);
            ldsm4i<0>(A[2], aA2); ldsm4i<0>(A[3], aA3);
            ldsm4i<0>(B[0], aB0); ldsm4i<0>(B[1], aB1);
            #pragma unroll
            for (int ma = 0; ma < 4; ++ma) {
                #pragma unroll
                for (int nb = 0; nb < 4; ++nb) {
                    s0 += ex2f(acc[ma][nb][0]);
                    s1 += ex2f(acc[ma][nb][1]);
                    s2 += ex2f(acc[ma][nb][2]);
                    s3 += ex2f(acc[ma][nb][3]);
                }
                #pragma unroll
                for (int nb = 0; nb < 4; ++nb)
                    mma_zro(acc[ma][nb], A[ma], &B[nb >> 1][(nb & 1) * 2]);
            }
        }
        facc += pw * ((s0 + s1) + (s2 + s3));  // pw=0 on first iteration

        KSTEP(32)
        KSTEP(64)
        KSTEP(96)

        pw = cdiag ? 1.0f : 2.0f;
        buf = nbuf;
    }

    // Final pending epilogue.
    {
        float s0 = 0.f, s1 = 0.f, s2 = 0.f, s3 = 0.f;
        #pragma unroll
        for (int ma = 0; ma < 4; ++ma)
            #pragma unroll
            for (int nb = 0; nb < 4; ++nb) {
                s0 += ex2f(acc[ma][nb][0]);
                s1 += ex2f(acc[ma][nb][1]);
                s2 += ex2f(acc[ma][nb][2]);
                s3 += ex2f(acc[ma][nb][3]);
            }
        facc += pw * ((s0 + s1) + (s2 + s3));
    }

    // One block reduction in double at the very end.
    double acc_d = (double)facc;
    #pragma unroll
    for (int o = 16; o > 0; o >>= 1)
        acc_d += __shfl_down_sync(0xffffffffu, acc_d, o);
    if (lid == 0) redbuf[wid] = acc_d;
    __syncthreads();
    if (tid == 0) {
        double v = ((redbuf[0] + redbuf[1]) + (redbuf[2] + redbuf[3])) +
                   ((redbuf[4] + redbuf[5]) + (redbuf[6] + redbuf[7]));
        g_partials[blockIdx.x] = v;
    }

    // Fused finalize: last CTA reduces per-batch and writes the loss.
    __threadfence();
    if (tid == 0) {
        unsigned o = atomicAdd(&g_cnt, 1u);
        is_last_s = (o == GRID - 1) ? 1 : 0;
    }
    __syncthreads();
    if (is_last_s) {
        __threadfence();
        const int w = wid;             // warp w handles batch w
        double s = 0.0;
        for (int i = lid; i < SLOTS; i += 32)
            s += g_partials[(i << 3) + w];
        #pragma unroll
        for (int o = 16; o > 0; o >>= 1)
            s += __shfl_down_sync(0xffffffffu, s, o);
        if (lid == 0) redbuf[w] = log(s);
        __syncthreads();
        if (tid == 0) {
            double L = ((redbuf[0] + redbuf[1]) + (redbuf[2] + redbuf[3])) +
                       ((redbuf[4] + redbuf[5]) + (redbuf[6] + redbuf[7]));
            *out = (float)(L / 8.0);
            g_cnt = 0;                 // reset for next graph replay
        }
    }
}

extern "C" void kernel_launch(void* const* d_in, const int* in_sizes, int n_in,
                              void* d_out, int out_size) {
    (void)in_sizes; (void)n_in; (void)out_size;
    const float* emb = (const float*)d_in[0];
    float* out = (float*)d_out;
    cudaFuncSetAttribute(tile_kernel, cudaFuncAttributeMaxDynamicSharedMemorySize, SMEM_BYTES);
    split_kernel<<<BATCH * NPTS * DIM / (256 * 4), 256>>>(emb);
    tile_kernel<<<GRID, TPB, SMEM_BYTES>>>(out);
}

// round 12
// speedup vs baseline: 1.4472x; 1.0070x over previous
#include <cuda_runtime.h>
#include <cuda_fp16.h>
#include <math.h>
#include <stdint.h>

#define BATCH 8
#define NPTS  4096
#define DIM   64
#define TILE  128
#define NT    (NPTS / TILE)            // 32
#define NTRI  (NT * (NT + 1) / 2)      // 528 upper-tri tiles per batch
#define SLOTS 37                       // CTAs per batch
#define GRID  (BATCH * SLOTS)          // 296
#define TPB   256

// smem sub-tile: 128 rows x 72 fp16 (144 B stride) -> conflict-free ldmatrix/STS
#define SROWB   144
#define SUBTILE (128 * SROWB)          // 18432 B
#define BUFSZ   (2 * SUBTILE)          // A+B = 36864 B
#define NBUF    3                      // triple buffer -> single barrier per tile
#define SMEM_BYTES (NBUF * BUFSZ)      // 110592 (2 CTAs/SM)

// Both operands from ONE array scaled by sqrt(0.5*log2(e)):
// (s*a)·(s*b) = 0.5*log2(e)*a·b  ->  ex2(acc) = exp(0.5*<a,b>)
__device__ __align__(16) __half g_s[BATCH * NPTS * DIM];
__device__ double g_partials[GRID];
__device__ unsigned g_cnt = 0;

__device__ __forceinline__ uint32_t smem_u32(const void* p) {
    uint32_t a;
    asm("{ .reg .u64 t; cvta.to.shared.u64 t, %1; cvt.u32.u64 %0, t; }" : "=r"(a) : "l"(p));
    return a;
}
template <int IMM>
__device__ __forceinline__ void ldsm4i(uint32_t* r, uint32_t addr) {
    asm volatile("ldmatrix.sync.aligned.m8n8.x4.shared.b16 {%0,%1,%2,%3}, [%4+%5];"
                 : "=r"(r[0]), "=r"(r[1]), "=r"(r[2]), "=r"(r[3])
                 : "r"(addr), "n"(IMM));
}
// NON-volatile MMA: ordering pinned by register dependencies only.
__device__ __forceinline__ void mma_acc(float* d, const uint32_t* a, const uint32_t* b) {
    asm("mma.sync.aligned.m16n8k16.row.col.f32.f16.f16.f32 "
        "{%0,%1,%2,%3}, {%4,%5,%6,%7}, {%8,%9}, {%0,%1,%2,%3};"
        : "+f"(d[0]), "+f"(d[1]), "+f"(d[2]), "+f"(d[3])
        : "r"(a[0]), "r"(a[1]), "r"(a[2]), "r"(a[3]), "r"(b[0]), "r"(b[1]));
}
// first-kstep variant: C = 0 -> writes acc fresh, no zeroing MOVs needed.
__device__ __forceinline__ void mma_zro(float* d, const uint32_t* a, const uint32_t* b) {
    asm("mma.sync.aligned.m16n8k16.row.col.f32.f16.f16.f32 "
        "{%0,%1,%2,%3}, {%4,%5,%6,%7}, {%8,%9}, {%10,%10,%10,%10};"
        : "=f"(d[0]), "=f"(d[1]), "=f"(d[2]), "=f"(d[3])
        : "r"(a[0]), "r"(a[1]), "r"(a[2]), "r"(a[3]), "r"(b[0]), "r"(b[1]), "f"(0.0f));
}
template <int DI, int SI>
__device__ __forceinline__ void cp16i(uint32_t dst, const __half* src) {
    asm volatile("cp.async.ca.shared.global [%0+%2], [%1+%3], 16;"
                 :: "r"(dst), "l"(src), "n"(DI), "n"(SI));
}
__device__ __forceinline__ float ex2f(float x) {
    float e;
    asm("ex2.approx.f32 %0, %1;" : "=f"(e) : "f"(x));
    return e;
}

// ---------------- 1) convert f32 -> fp16 scaled by sqrt(0.5*log2e) ----------------
__global__ __launch_bounds__(256) void split_kernel(const float* __restrict__ emb) {
    const float SQC = 0.84932180612318867f;  // sqrt(0.5*log2(e))
    int i = (blockIdx.x * 256 + threadIdx.x) * 4;
    float4 v = *(const float4*)(emb + i);
    float x[4] = {v.x, v.y, v.z, v.w};
    __half s[4];
    #pragma unroll
    for (int j = 0; j < 4; ++j) s[j] = __float2half(x[j] * SQC);
    *(uint2*)&g_s[i] = *(uint2*)s;
}

// ---------------- 2) persistent HMMA tile kernel (fused finalize) ----------------
__device__ __forceinline__ void load_tile(uint32_t dstA, const __half* sA, const __half* sB,
                                          bool dg) {
    cp16i<0 * SROWB, 0 * DIM * 2>(dstA, sA);
    cp16i<32 * SROWB, 32 * DIM * 2>(dstA, sA);
    cp16i<64 * SROWB, 64 * DIM * 2>(dstA, sA);
    cp16i<96 * SROWB, 96 * DIM * 2>(dstA, sA);
    if (!dg) {   // diagonal tile: B region = A region, skip the B load
        cp16i<SUBTILE + 0 * SROWB, 0 * DIM * 2>(dstA, sB);
        cp16i<SUBTILE + 32 * SROWB, 32 * DIM * 2>(dstA, sB);
        cp16i<SUBTILE + 64 * SROWB, 64 * DIM * 2>(dstA, sB);
        cp16i<SUBTILE + 96 * SROWB, 96 * DIM * 2>(dstA, sB);
    }
    asm volatile("cp.async.commit_group;" ::: "memory");
}

// One tile's compute, k-steps rotated to start at R (R in {0,2}).
// First k-step (KO=R*32) uses mma_zro and interleaves the PREVIOUS tile's
// ex2 epilogue chunk-by-chunk ahead of the acc overwrite.
template <int R>
__device__ __forceinline__ void do_tile(
    float acc[4][4][4], float& facc, float pw,
    uint32_t aA0, uint32_t aA1, uint32_t aA2, uint32_t aA3,
    uint32_t aB0, uint32_t aB1)
{
    constexpr int K0 = (R & 3) * 32;
    constexpr int K1 = ((R + 1) & 3) * 32;
    constexpr int K2 = ((R + 2) & 3) * 32;
    constexpr int K3 = ((R + 3) & 3) * 32;

    float s0 = 0.f, s1 = 0.f, s2 = 0.f, s3 = 0.f;
    {
        uint32_t A[4][4], B[2][4];
        ldsm4i<K0>(A[0], aA0); ldsm4i<K0>(A[1], aA1);
        ldsm4i<K0>(A[2], aA2); ldsm4i<K0>(A[3], aA3);
        ldsm4i<K0>(B[0], aB0); ldsm4i<K0>(B[1], aB1);
        #pragma unroll
        for (int ma = 0; ma < 4; ++ma) {
            #pragma unroll
            for (int nb = 0; nb < 4; ++nb) {
                s0 += ex2f(acc[ma][nb][0]);
                s1 += ex2f(acc[ma][nb][1]);
                s2 += ex2f(acc[ma][nb][2]);
                s3 += ex2f(acc[ma][nb][3]);
            }
            #pragma unroll
            for (int nb = 0; nb < 4; ++nb)
                mma_zro(acc[ma][nb], A[ma], &B[nb >> 1][(nb & 1) * 2]);
        }
    }
    facc += pw * ((s0 + s1) + (s2 + s3));  // pw=0 on first iteration

    #define KSTEP_T(KO)                                                           \
    {                                                                             \
        uint32_t A[4][4], B[2][4];                                                \
        ldsm4i<KO>(A[0], aA0); ldsm4i<KO>(A[1], aA1);                             \
        ldsm4i<KO>(A[2], aA2); ldsm4i<KO>(A[3], aA3);                             \
        ldsm4i<KO>(B[0], aB0); ldsm4i<KO>(B[1], aB1);                             \
        _Pragma("unroll")                                                         \
        for (int ma = 0; ma < 4; ++ma)                                            \
            _Pragma("unroll")                                                     \
            for (int nb = 0; nb < 4; ++nb)                                        \
                mma_acc(acc[ma][nb], A[ma], &B[nb >> 1][(nb & 1) * 2]);           \
    }
    KSTEP_T(K1)
    KSTEP_T(K2)
    KSTEP_T(K3)
    #undef KSTEP_T
}

__global__ __launch_bounds__(TPB, 2) void tile_kernel(float* __restrict__ out) {
    extern __shared__ __align__(128) char smem[];
    __shared__ double redbuf[8];
    __shared__ int is_last_s;
    const uint32_t sbase = smem_u32(smem);
    const int tid = threadIdx.x;
    const int wid = tid >> 5;
    const int lid = tid & 31;
    const int wm = wid & 1;            // 2 warps along M (64 rows each)
    const int wn = wid >> 1;           // 4 warps along N (32 cols each)
    const bool hi = (wid >= 4);        // phase group: hi warps start at kstep 2

    const int bb   = blockIdx.x & 7;   // fixed batch per CTA
    const int slot = blockIdx.x >> 3;  // 0..36
    const __half* gS = g_s + (size_t)bb * NPTS * DIM;

    const int srcoff = (tid >> 3) * DIM + (tid & 7) * 8;                 // elements
    const uint32_t dsto = (uint32_t)((tid >> 3) * SROWB + (tid & 7) * 16);

    uint32_t offA[4];
    {
        int row = ((lid >> 3) & 1) * 8 + (lid & 7);
        int kc  = (lid >> 4) * 8;
        #pragma unroll
        for (int ma = 0; ma < 4; ++ma)
            offA[ma] = (uint32_t)((wm * 64 + ma * 16 + row) * SROWB + kc * 2);
    }
    uint32_t offB[2];   // WITHOUT the SUBTILE base (added per tile; diag -> A region)
    {
        int row = (lid >> 4) * 8 + (lid & 7);
        int kc  = ((lid >> 3) & 1) * 8;
        #pragma unroll
        for (int np = 0; np < 2; ++np)
            offB[np] = (uint32_t)((wn * 32 + np * 16 + row) * SROWB + kc * 2);
    }

    float facc = 0.0f;                 // running per-thread sum (all positive)
    float pw   = 0.0f;                 // weight of pending (previous) tile; 0 = none
    float acc[4][4][4];
    #pragma unroll
    for (int i = 0; i < 4; ++i)
        #pragma unroll
        for (int j = 0; j < 4; ++j)
            #pragma unroll
            for (int e = 0; e < 4; ++e) acc[i][j][e] = 0.0f;

    // Incremental triangular decode: tt = tm(tm+1)/2 + tn, 0 <= tn <= tm.
    int tn = slot, tm = 0;
    while (tn > tm) { tn -= (tm + 1); ++tm; }

    load_tile(sbase + dsto, gS + tn * (TILE * DIM) + srcoff,
              gS + tm * (TILE * DIM) + srcoff, tn == tm);

    int buf = 0;
    for (int tt = slot; tt < NTRI; tt += SLOTS) {
        const int cdiag = (tn == tm);
        const int nbuf = (buf == NBUF - 1) ? 0 : buf + 1;
        if (tt + SLOTS < NTRI) {
            tn += SLOTS;
            while (tn > tm) { tn -= (tm + 1); ++tm; }
            load_tile(sbase + nbuf * BUFSZ + dsto,
                      gS + tn * (TILE * DIM) + srcoff,
                      gS + tm * (TILE * DIM) + srcoff, tn == tm);
            asm volatile("cp.async.wait_group 1;" ::: "memory");
        } else {
            asm volatile("cp.async.wait_group 0;" ::: "memory");
        }
        __syncthreads();               // single barrier: data ready; WAR safe at depth 3

        const uint32_t bufbase = sbase + buf * BUFSZ;
        const uint32_t aA0 = bufbase + offA[0], aA1 = bufbase + offA[1];
        const uint32_t aA2 = bufbase + offA[2], aA3 = bufbase + offA[3];
        const uint32_t bB  = bufbase + (cdiag ? 0u : (uint32_t)SUBTILE);
        const uint32_t aB0 = bB + offB[0], aB1 = bB + offB[1];

        if (hi)
            do_tile<2>(acc, facc, pw, aA0, aA1, aA2, aA3, aB0, aB1);
        else
            do_tile<0>(acc, facc, pw, aA0, aA1, aA2, aA3, aB0, aB1);

        pw = cdiag ? 1.0f : 2.0f;
        buf = nbuf;
    }

    // Final pending epilogue.
    {
        float s0 = 0.f, s1 = 0.f, s2 = 0.f, s3 = 0.f;
        #pragma unroll
        for (int ma = 0; ma < 4; ++ma)
            #pragma unroll
            for (int nb = 0; nb < 4; ++nb) {
                s0 += ex2f(acc[ma][nb][0]);
                s1 += ex2f(acc[ma][nb][1]);
                s2 += ex2f(acc[ma][nb][2]);
                s3 += ex2f(acc[ma][nb][3]);
            }
        facc += pw * ((s0 + s1) + (s2 + s3));
    }

    // One block reduction in double at the very end.
    double acc_d = (double)facc;
    #pragma unroll
    for (int o = 16; o > 0; o >>= 1)
        acc_d += __shfl_down_sync(0xffffffffu, acc_d, o);
    if (lid == 0) redbuf[wid] = acc_d;
    __syncthreads();
    if (tid == 0) {
        double v = ((redbuf[0] + redbuf[1]) + (redbuf[2] + redbuf[3])) +
                   ((redbuf[4] + redbuf[5]) + (redbuf[6] + redbuf[7]));
        g_partials[blockIdx.x] = v;
    }

    // Fused finalize: last CTA reduces per-batch and writes the loss.
    __threadfence();
    if (tid == 0) {
        unsigned o = atomicAdd(&g_cnt, 1u);
        is_last_s = (o == GRID - 1) ? 1 : 0;
    }
    __syncthreads();
    if (is_last_s) {
        __threadfence();
        const int w = wid;             // warp w handles batch w
        double s = 0.0;
        for (int i = lid; i < SLOTS; i += 32)
            s += g_partials[(i << 3) + w];
        #pragma unroll
        for (int o = 16; o > 0; o >>= 1)
            s += __shfl_down_sync(0xffffffffu, s, o);
        if (lid == 0) redbuf[w] = log(s);
        __syncthreads();
        if (tid == 0) {
            double L = ((redbuf[0] + redbuf[1]) + (redbuf[2] + redbuf[3])) +
                       ((redbuf[4] + redbuf[5]) + (redbuf[6] + redbuf[7]));
            *out = (float)(L / 8.0);
            g_cnt = 0;                 // reset for next graph replay
        }
    }
}

extern "C" void kernel_launch(void* const* d_in, const int* in_sizes, int n_in,
                              void* d_out, int out_size) {
    (void)in_sizes; (void)n_in; (void)out_size;
    const float* emb = (const float*)d_in[0];
    float* out = (float*)d_out;
    cudaFuncSetAttribute(tile_kernel, cudaFuncAttributeMaxDynamicSharedMemorySize, SMEM_BYTES);
    split_kernel<<<BATCH * NPTS * DIM / (256 * 4), 256>>>(emb);
    tile_kernel<<<GRID, TPB, SMEM_BYTES>>>(out);
}